// round 16
// baseline (speedup 1.0000x reference)
#include <cuda_runtime.h>
#include <cuda_bf16.h>
#include <math.h>
#include <stdint.h>

#define S_LEN 2048
#define HID   4096
#define NH    32
#define NKV   8
#define HDIM  128
#define WINDOW 1024
#define KDIM  4096
#define NKVD  (NKV * HDIM)      // 1024

// ---------------- scratch (__device__ globals; no allocation) ----------------
// int8 2-level quant buffers + per-row scales
__device__ __align__(256) int8_t g_hs8h[S_LEN * HID];
__device__ __align__(256) int8_t g_hs8l[S_LEN * HID];
__device__ __align__(256) int8_t g_Wq8h[HID * HID];
__device__ __align__(256) int8_t g_Wq8l[HID * HID];
__device__ __align__(256) int8_t g_Wk8h[NKVD * HID];
__device__ __align__(256) int8_t g_Wk8l[NKVD * HID];
__device__ __align__(256) int8_t g_Wv8h[NKVD * HID];
__device__ __align__(256) int8_t g_Wv8l[NKVD * HID];
__device__ __align__(256) int8_t g_Wo8h[HID * HID];
__device__ __align__(256) int8_t g_Wo8l[HID * HID];
__device__ __align__(256) int8_t g_att8h[S_LEN * HID];
__device__ __align__(256) int8_t g_att8l[S_LEN * HID];
__device__ float g_s_hs[S_LEN];
__device__ float g_s_Wq[HID];
__device__ float g_s_Wk[NKVD];
__device__ float g_s_Wv[NKVD];
__device__ float g_s_Wo[HID];
__device__ float g_s_att[S_LEN];
__device__ __align__(256) float g_att[S_LEN * HID];
// bf16 hi/lo Q/K/V for attention (produced by QKV epilogue)
__device__ __align__(256) __nv_bfloat16 g_Qh[S_LEN * HID];
__device__ __align__(256) __nv_bfloat16 g_Ql[S_LEN * HID];
__device__ __align__(256) __nv_bfloat16 g_Kh[S_LEN * NKVD];
__device__ __align__(256) __nv_bfloat16 g_Kl[S_LEN * NKVD];
__device__ __align__(256) __nv_bfloat16 g_Vh[S_LEN * NKVD];
__device__ __align__(256) __nv_bfloat16 g_Vl[S_LEN * NKVD];

// ---------------- helpers ----------------
__device__ __forceinline__ uint32_t smem_u32(const void* p) {
    uint32_t a;
    asm("{ .reg .u64 t; cvta.to.shared.u64 t, %1; cvt.u32.u64 %0, t; }" : "=r"(a) : "l"(p));
    return a;
}
__device__ __forceinline__ void cp16(uint32_t dst, const void* src) {
    asm volatile("cp.async.cg.shared.global [%0], [%1], 16;" :: "r"(dst), "l"(src));
}
__device__ __forceinline__ void cp_commit() {
    asm volatile("cp.async.commit_group;" ::: "memory");
}
template <int N>
__device__ __forceinline__ void cp_wait() {
    asm volatile("cp.async.wait_group %0;" :: "n"(N) : "memory");
}
__device__ __forceinline__ void ldsm_x4(uint32_t* r, uint32_t addr) {
    asm volatile("ldmatrix.sync.aligned.m8n8.x4.shared.b16 {%0,%1,%2,%3}, [%4];"
                 : "=r"(r[0]), "=r"(r[1]), "=r"(r[2]), "=r"(r[3]) : "r"(addr));
}
__device__ __forceinline__ void ldsm_x4_t(uint32_t* r, uint32_t addr) {
    asm volatile("ldmatrix.sync.aligned.m8n8.x4.trans.shared.b16 {%0,%1,%2,%3}, [%4];"
                 : "=r"(r[0]), "=r"(r[1]), "=r"(r[2]), "=r"(r[3]) : "r"(addr));
}
__device__ __forceinline__ void mma16816(float* c, const uint32_t* a,
                                         uint32_t b0, uint32_t b1) {
    asm("mma.sync.aligned.m16n8k16.row.col.f32.bf16.bf16.f32 "
        "{%0,%1,%2,%3}, {%4,%5,%6,%7}, {%8,%9}, {%0,%1,%2,%3};"
        : "+f"(c[0]), "+f"(c[1]), "+f"(c[2]), "+f"(c[3])
        : "r"(a[0]), "r"(a[1]), "r"(a[2]), "r"(a[3]), "r"(b0), "r"(b1));
}
__device__ __forceinline__ void mma_s8(int* c, const uint32_t* a,
                                       uint32_t b0, uint32_t b1) {
    asm("mma.sync.aligned.m16n8k32.row.col.s32.s8.s8.s32 "
        "{%0,%1,%2,%3}, {%4,%5,%6,%7}, {%8,%9}, {%0,%1,%2,%3};"
        : "+r"(c[0]), "+r"(c[1]), "+r"(c[2]), "+r"(c[3])
        : "r"(a[0]), "r"(a[1]), "r"(a[2]), "r"(a[3]), "r"(b0), "r"(b1));
}
__device__ __forceinline__ void packsplit(float x, float y, uint32_t& hi, uint32_t& lo) {
    __nv_bfloat16 hx = __float2bfloat16(x), hy = __float2bfloat16(y);
    __nv_bfloat16 lx = __float2bfloat16(x - __bfloat162float(hx));
    __nv_bfloat16 ly = __float2bfloat16(y - __bfloat162float(hy));
    hi = (uint32_t)__bfloat16_as_ushort(hx) | ((uint32_t)__bfloat16_as_ushort(hy) << 16);
    lo = (uint32_t)__bfloat16_as_ushort(lx) | ((uint32_t)__bfloat16_as_ushort(ly) << 16);
}

#define SWZ(off) ((off) ^ (((off) >> 3) & 0x70))

// ---------------------------------------------------------------------------
// per-row 2-level int8 quantization: x = s*(hi8 + lo8/128). One warp per row
// of 4096 floats.
// ---------------------------------------------------------------------------
__device__ __forceinline__ void quant_row_warp(const float* __restrict__ row,
        int8_t* __restrict__ qh, int8_t* __restrict__ ql, float* __restrict__ sc,
        int lane)
{
    const float4* r4 = (const float4*)row;
    float mx = 0.f;
    #pragma unroll
    for (int i = 0; i < 32; ++i) {
        float4 v = r4[lane + i * 32];
        mx = fmaxf(mx, fmaxf(fmaxf(fabsf(v.x), fabsf(v.y)),
                             fmaxf(fabsf(v.z), fabsf(v.w))));
    }
    #pragma unroll
    for (int d = 16; d; d >>= 1) mx = fmaxf(mx, __shfl_xor_sync(0xffffffffu, mx, d));
    float s    = (mx > 0.f) ? mx * (1.f / 127.f) : 1.f;
    float invs = (mx > 0.f) ? 127.f / mx : 0.f;
    char4* oh = (char4*)qh;
    char4* ol = (char4*)ql;
    #pragma unroll
    for (int i = 0; i < 32; ++i) {
        float4 v = r4[lane + i * 32];
        float x[4] = {v.x, v.y, v.z, v.w};
        signed char h[4], l[4];
        #pragma unroll
        for (int j = 0; j < 4; ++j) {
            int hi = __float2int_rn(x[j] * invs);
            float res = x[j] - (float)hi * s;
            int lo = __float2int_rn(res * invs * 128.f);
            h[j] = (signed char)hi;
            l[j] = (signed char)lo;
        }
        oh[lane + i * 32] = make_char4(h[0], h[1], h[2], h[3]);
        ol[lane + i * 32] = make_char4(l[0], l[1], l[2], l[3]);
    }
    if (lane == 0) *sc = s;
}

#define NROWS_ALL (S_LEN + HID + NKVD + NKVD + HID)   // 12288

__global__ void quant_all(const float* __restrict__ hs, const float* __restrict__ Wq,
                          const float* __restrict__ Wk, const float* __restrict__ Wv,
                          const float* __restrict__ Wo)
{
    int gw = (blockIdx.x * blockDim.x + threadIdx.x) >> 5;
    int lane = threadIdx.x & 31;
    if (gw >= NROWS_ALL) return;
    const float* in; int8_t *qh, *ql; float* sc; int r;
    if (gw < S_LEN)                       { r = gw;                 in = hs; qh = g_hs8h; ql = g_hs8l; sc = g_s_hs; }
    else if (gw < S_LEN + HID)            { r = gw - S_LEN;         in = Wq; qh = g_Wq8h; ql = g_Wq8l; sc = g_s_Wq; }
    else if (gw < S_LEN + HID + NKVD)     { r = gw - S_LEN - HID;   in = Wk; qh = g_Wk8h; ql = g_Wk8l; sc = g_s_Wk; }
    else if (gw < S_LEN + HID + 2 * NKVD) { r = gw - S_LEN - HID - NKVD; in = Wv; qh = g_Wv8h; ql = g_Wv8l; sc = g_s_Wv; }
    else                                  { r = gw - S_LEN - HID - 2 * NKVD; in = Wo; qh = g_Wo8h; ql = g_Wo8l; sc = g_s_Wo; }
    size_t off = (size_t)r * KDIM;
    quant_row_warp(in + off, qh + off, ql + off, sc + r, lane);
}

__global__ void quant_att_k()
{
    int gw = (blockIdx.x * blockDim.x + threadIdx.x) >> 5;
    int lane = threadIdx.x & 31;
    if (gw >= S_LEN) return;
    size_t off = (size_t)gw * HID;
    quant_row_warp(g_att + off, g_att8h + off, g_att8l + off, g_s_att + gw, lane);
}

// ---------------------------------------------------------------------------
// int8 GEMM: 256 threads (8 warps), warp tile 64x32, CTA tile 128x128,
// K-chunk 128 bytes, 3-stage cp.async pipeline. s8 k32 fragments share the
// bf16 k16 byte layout, so ldsm addressing is unchanged.
// acc1 = hh; acc2 = hl + lh (same scale sa*sb/128, exact int add).
// ---------------------------------------------------------------------------
#define GKB 128
#define TILEB 16384
#define BUFB (4 * TILEB)
#define NSTAGE 3
#define GEMM_SMEM (1024 + NSTAGE * BUFB)
#define NTHR 256

#define I8_COMPUTE(bufb)                                                          \
    _Pragma("unroll")                                                             \
    for (int ks = 0; ks < 4; ++ks) {                                              \
        uint32_t ah[4][4], al[4][4], bh[2][4], bl[2][4];                          \
        _Pragma("unroll")                                                         \
        for (int mi = 0; mi < 4; ++mi) {                                          \
            uint32_t off = (uint32_t)((wr * 64 + mi * 16 + lrow) * 128 + ks * 32 + lkb); \
            uint32_t sw = SWZ(off);                                               \
            ldsm_x4(ah[mi], (bufb) + sw);                                         \
            ldsm_x4(al[mi], (bufb) + TILEB + sw);                                 \
        }                                                                         \
        _Pragma("unroll")                                                         \
        for (int np = 0; np < 2; ++np) {                                          \
            uint32_t off = (uint32_t)((wc * 32 + np * 16 + lrow) * 128 + ks * 32 + lkb); \
            uint32_t sw = SWZ(off);                                               \
            ldsm_x4(bh[np], (bufb) + 2 * TILEB + sw);                             \
            ldsm_x4(bl[np], (bufb) + 3 * TILEB + sw);                             \
        }                                                                         \
        _Pragma("unroll")                                                         \
        for (int mi = 0; mi < 4; ++mi)                                            \
            _Pragma("unroll")                                                     \
            for (int ni = 0; ni < 4; ++ni)                                        \
                mma_s8(acc1[mi][ni], ah[mi],                                      \
                       bh[ni >> 1][ni & 1], bh[ni >> 1][2 + (ni & 1)]);           \
        _Pragma("unroll")                                                         \
        for (int mi = 0; mi < 4; ++mi)                                            \
            _Pragma("unroll")                                                     \
            for (int ni = 0; ni < 4; ++ni)                                        \
                mma_s8(acc2[mi][ni], ah[mi],                                      \
                       bl[ni >> 1][ni & 1], bl[ni >> 1][2 + (ni & 1)]);           \
        _Pragma("unroll")                                                         \
        for (int mi = 0; mi < 4; ++mi)                                            \
            _Pragma("unroll")                                                     \
            for (int ni = 0; ni < 4; ++ni)                                        \
                mma_s8(acc2[mi][ni], al[mi],                                      \
                       bh[ni >> 1][ni & 1], bh[ni >> 1][2 + (ni & 1)]);           \
    }

#define I8_LOADER(NAME, AH, AL, BH, BL, AROW, BROW)                               \
    auto NAME = [&](int it) {                                                     \
        const uint32_t bufb = sbase + (it % NSTAGE) * BUFB;                       \
        const int k0 = it * GKB;                                                  \
        _Pragma("unroll")                                                         \
        for (int p = 0; p < 4; ++p) {                                             \
            int linear = tid + p * NTHR;                                          \
            int r = linear >> 3;                                                  \
            int cb = (linear & 7) * 16;                                           \
            uint32_t sw = SWZ((uint32_t)(r * 128 + cb));                          \
            size_t ga = (size_t)(AROW + r) * KDIM + k0 + cb;                      \
            size_t gb = (size_t)(BROW + r) * KDIM + k0 + cb;                      \
            cp16(bufb + sw,              &(AH)[ga]);                              \
            cp16(bufb + TILEB + sw,      &(AL)[ga]);                              \
            cp16(bufb + 2 * TILEB + sw,  &(BH)[gb]);                              \
            cp16(bufb + 3 * TILEB + sw,  &(BL)[gb]);                              \
        }                                                                         \
    };

// ---------------------------------------------------------------------------
// Fused QKV projection (int8) + dequant + RoPE + bf16 hi/lo split epilogue.
// grid (48, 16): bx 0..31 Q, 32..39 K, 40..47 V.
// ---------------------------------------------------------------------------
__global__ void __launch_bounds__(NTHR, 1)
gemm_qkv_i8(const int* __restrict__ pos)
{
    extern __shared__ char smraw[];
    char* smc = (char*)(((uintptr_t)smraw + 1023) & ~(uintptr_t)1023);
    const uint32_t sbase = smem_u32(smc);

    const int tid = threadIdx.x;
    const int lane = tid & 31;
    const int wid = tid >> 5;
    const int wr = wid >> 2;
    const int wc = wid & 3;
    const int bx = blockIdx.x;
    const int m0 = blockIdx.y * 128;

    const int8_t *Bh, *Bl;
    const float* sB;
    int bn0;
    if (bx < 32)      { Bh = g_Wq8h; Bl = g_Wq8l; sB = g_s_Wq + bx * 128;        bn0 = bx * 128; }
    else if (bx < 40) { Bh = g_Wk8h; Bl = g_Wk8l; sB = g_s_Wk + (bx - 32) * 128; bn0 = (bx - 32) * 128; }
    else              { Bh = g_Wv8h; Bl = g_Wv8l; sB = g_s_Wv + (bx - 40) * 128; bn0 = (bx - 40) * 128; }

    int acc1[4][4][4], acc2[4][4][4];
    #pragma unroll
    for (int a = 0; a < 4; ++a)
        #pragma unroll
        for (int b = 0; b < 4; ++b)
            #pragma unroll
            for (int c = 0; c < 4; ++c) { acc1[a][b][c] = 0; acc2[a][b][c] = 0; }

    const int NCHUNK = KDIM / GKB;   // 32
    I8_LOADER(load_chunk, g_hs8h, g_hs8l, Bh, Bl, m0, bn0)

    load_chunk(0); cp_commit();
    load_chunk(1); cp_commit();

    const int lrow = lane & 15;
    const int lkb  = (lane >> 4) * 16;

    for (int it = 0; it < NCHUNK; ++it) {
        cp_wait<1>();
        __syncthreads();
        if (it + 2 < NCHUNK) load_chunk(it + 2);
        cp_commit();
        const uint32_t bufb = sbase + (it % NSTAGE) * BUFB;
        I8_COMPUTE(bufb)
    }

    __syncthreads();

    // dequant + stage to smem
    float* Cs = (float*)smc;           // 128 x 132 floats
    {
        const int rb = wr * 64 + (lane >> 2);
        const int cb2 = wc * 32 + (lane & 3) * 2;
        #pragma unroll
        for (int mi = 0; mi < 4; ++mi) {
            int r = rb + mi * 16;
            float sa0 = g_s_hs[m0 + r];
            float sa1 = g_s_hs[m0 + r + 8];
            #pragma unroll
            for (int ni = 0; ni < 4; ++ni) {
                int cc = cb2 + ni * 8;
                float sb0 = sB[cc], sb1 = sB[cc + 1];
                Cs[r * 132 + cc]           = sa0 * sb0 * ((float)acc1[mi][ni][0] + (float)acc2[mi][ni][0] * 0.0078125f);
                Cs[r * 132 + cc + 1]       = sa0 * sb1 * ((float)acc1[mi][ni][1] + (float)acc2[mi][ni][1] * 0.0078125f);
                Cs[(r + 8) * 132 + cc]     = sa1 * sb0 * ((float)acc1[mi][ni][2] + (float)acc2[mi][ni][2] * 0.0078125f);
                Cs[(r + 8) * 132 + cc + 1] = sa1 * sb1 * ((float)acc1[mi][ni][3] + (float)acc2[mi][ni][3] * 0.0078125f);
            }
        }
    }
    __syncthreads();

    __nv_bfloat16 *Hout, *Lout;
    int stride, off;
    bool dorope;
    if (bx < 32)      { Hout = g_Qh; Lout = g_Ql; stride = HID;  off = bx * 128;        dorope = true; }
    else if (bx < 40) { Hout = g_Kh; Lout = g_Kl; stride = NKVD; off = (bx - 32) * 128; dorope = true; }
    else              { Hout = g_Vh; Lout = g_Vl; stride = NKVD; off = (bx - 40) * 128; dorope = false; }

    const int d0 = tid & 63;
    const int rg = tid >> 6;
    const float invf = dorope ? expf(-(float)d0 * 0.14391156831212787f) : 0.f;

    #pragma unroll 4
    for (int rr = 0; rr < 32; ++rr) {
        const int r = rg * 32 + rr;
        const int t = m0 + r;
        float x0 = Cs[r * 132 + d0];
        float x1 = Cs[r * 132 + d0 + 64];
        float y0, y1;
        if (dorope) {
            float s, c;
            sincosf((float)pos[t] * invf, &s, &c);
            y0 = x0 * c - x1 * s;
            y1 = x1 * c + x0 * s;
        } else {
            y0 = x0; y1 = x1;
        }
        __nv_bfloat16 h0 = __float2bfloat16(y0);
        __nv_bfloat16 l0 = __float2bfloat16(y0 - __bfloat162float(h0));
        __nv_bfloat16 h1 = __float2bfloat16(y1);
        __nv_bfloat16 l1 = __float2bfloat16(y1 - __bfloat162float(h1));
        size_t o = (size_t)t * stride + off + d0;
        Hout[o]      = h0;
        Lout[o]      = l0;
        Hout[o + 64] = h1;
        Lout[o + 64] = l1;
    }
}

// ---------------------------------------------------------------------------
// Wo projection (int8): out = att @ Wo^T, fp32 out with dequant.
// ---------------------------------------------------------------------------
__global__ void __launch_bounds__(NTHR, 1)
gemm_wo_i8(float* __restrict__ C)
{
    extern __shared__ char smraw[];
    char* smc = (char*)(((uintptr_t)smraw + 1023) & ~(uintptr_t)1023);
    const uint32_t sbase = smem_u32(smc);

    const int tid = threadIdx.x;
    const int lane = tid & 31;
    const int wid = tid >> 5;
    const int wr = wid >> 2;
    const int wc = wid & 3;
    const int m0 = blockIdx.y * 128;
    const int n0 = blockIdx.x * 128;

    int acc1[4][4][4], acc2[4][4][4];
    #pragma unroll
    for (int a = 0; a < 4; ++a)
        #pragma unroll
        for (int b = 0; b < 4; ++b)
            #pragma unroll
            for (int c = 0; c < 4; ++c) { acc1[a][b][c] = 0; acc2[a][b][c] = 0; }

    const int NCHUNK = KDIM / GKB;
    I8_LOADER(load_chunk, g_att8h, g_att8l, g_Wo8h, g_Wo8l, m0, n0)

    load_chunk(0); cp_commit();
    load_chunk(1); cp_commit();

    const int lrow = lane & 15;
    const int lkb  = (lane >> 4) * 16;

    for (int it = 0; it < NCHUNK; ++it) {
        cp_wait<1>();
        __syncthreads();
        if (it + 2 < NCHUNK) load_chunk(it + 2);
        cp_commit();
        const uint32_t bufb = sbase + (it % NSTAGE) * BUFB;
        I8_COMPUTE(bufb)
    }

    const int row_base = m0 + wr * 64 + (lane >> 2);
    const int col_base = n0 + wc * 32 + (lane & 3) * 2;
    #pragma unroll
    for (int mi = 0; mi < 4; ++mi) {
        int r = row_base + mi * 16;
        float sa0 = g_s_att[r];
        float sa1 = g_s_att[r + 8];
        #pragma unroll
        for (int ni = 0; ni < 4; ++ni) {
            int cc = col_base + ni * 8;
            float sb0 = g_s_Wo[cc], sb1 = g_s_Wo[cc + 1];
            *(float2*)&C[(size_t)r * HID + cc] = make_float2(
                sa0 * sb0 * ((float)acc1[mi][ni][0] + (float)acc2[mi][ni][0] * 0.0078125f),
                sa0 * sb1 * ((float)acc1[mi][ni][1] + (float)acc2[mi][ni][1] * 0.0078125f));
            *(float2*)&C[(size_t)(r + 8) * HID + cc] = make_float2(
                sa1 * sb0 * ((float)acc1[mi][ni][2] + (float)acc2[mi][ni][2] * 0.0078125f),
                sa1 * sb1 * ((float)acc1[mi][ni][3] + (float)acc2[mi][ni][3] * 0.0078125f));
        }
    }
}

// ---------------------------------------------------------------------------
// Flash attention on tensor cores (bf16x3, online softmax in registers).
// Writes fp32 att output. 256 threads.
// ---------------------------------------------------------------------------
#define ATT_SMEM (1024 + 3 * 65536)

__global__ void __launch_bounds__(256)
attn_mma(const __nv_bfloat16* __restrict__ Qh_g, const __nv_bfloat16* __restrict__ Ql_g,
         const __nv_bfloat16* __restrict__ Kh_g, const __nv_bfloat16* __restrict__ Kl_g,
         const __nv_bfloat16* __restrict__ Vh_g, const __nv_bfloat16* __restrict__ Vl_g,
         float* __restrict__ O_g)
{
    extern __shared__ char smraw[];
    char* smc = (char*)(((uintptr_t)smraw + 1023) & ~(uintptr_t)1023);
    const uint32_t qbase = smem_u32(smc);
    const uint32_t kvbase = qbase + 65536;

    const int tid = threadIdx.x;
    const int lane = tid & 31;
    const int w = tid >> 5;
    const int wm = w * 16;
    const int m0 = blockIdx.x * 128;
    const int h = blockIdx.y;
    const int kvh = h >> 2;
    const int lrow = lane & 15;
    const int lhi = (lane >> 4) * 16;

    auto load_q = [&]() {
        #pragma unroll
        for (int p = 0; p < 16; ++p) {
            int lin = tid + p * 256;
            int t2 = lin >> 11;
            int rem = lin & 2047;
            int row = rem >> 4;
            int c = rem & 15;
            int half = c >> 3;
            int cb = (c & 7) * 16;
            uint32_t dst = qbase + t2 * 32768 + half * 16384
                         + SWZ((uint32_t)(row * 128 + cb));
            size_t elem = (size_t)(m0 + row) * HID + h * HDIM + half * 64 + (c & 7) * 8;
            cp16(dst, (t2 ? Ql_g : Qh_g) + elem);
        }
    };
    auto load_kv = [&](int j, int b) {
        const uint32_t base = kvbase + b * 65536;
        #pragma unroll
        for (int p = 0; p < 16; ++p) {
            int lin = tid + p * 256;
            int t4 = lin >> 10;
            int rem = lin & 1023;
            int row = rem >> 4;
            int c = rem & 15;
            int half = c >> 3;
            int cb = (c & 7) * 16;
            uint32_t dst = base + t4 * 16384 + half * 8192
                         + SWZ((uint32_t)(row * 128 + cb));
            size_t elem = (size_t)(j * 64 + row) * NKVD + kvh * HDIM
                        + half * 64 + (c & 7) * 8;
            const __nv_bfloat16* src =
                (t4 < 2) ? ((t4 & 1) ? Kl_g : Kh_g) : ((t4 & 1) ? Vl_g : Vh_g);
            cp16(dst, src + elem);
        }
    };

    const int j0 = (m0 >= 1024) ? (m0 - 1023) / 64 : 0;
    const int jend = m0 / 64 + 1;

    load_q();
    load_kv(j0, 0);
    cp_commit();

    float o[16][4];
    #pragma unroll
    for (int i = 0; i < 16; ++i)
        #pragma unroll
        for (int c = 0; c < 4; ++c) o[i][c] = 0.f;
    float mst0 = -INFINITY, mst1 = -INFINITY, lst0 = 0.f, lst1 = 0.f;

    const int row0 = m0 + wm + (lane >> 2);
    const int row1 = row0 + 8;
    const float scale = 0.08838834764831845f;

    for (int j = j0; j <= jend; ++j) {
        const int b = (j - j0) & 1;
        if (j + 1 <= jend) {
            load_kv(j + 1, b ^ 1);
            cp_commit();
            cp_wait<1>();
        } else {
            cp_wait<0>();
        }
        __syncthreads();

        const uint32_t kvb = kvbase + b * 65536;

        float sf[8][4];
        #pragma unroll
        for (int i = 0; i < 8; ++i)
            #pragma unroll
            for (int c = 0; c < 4; ++c) sf[i][c] = 0.f;

        #pragma unroll
        for (int kd = 0; kd < 8; ++kd) {
            const int half = kd >> 2;
            const uint32_t koff = (uint32_t)((kd & 3) * 32 + lhi);
            uint32_t ah[4], al[4], bh[4][4], bl[4][4];
            {
                uint32_t sw = SWZ((uint32_t)((wm + lrow) * 128) + koff);
                ldsm_x4(ah, qbase + half * 16384 + sw);
                ldsm_x4(al, qbase + 32768 + half * 16384 + sw);
            }
            #pragma unroll
            for (int nb = 0; nb < 4; ++nb) {
                uint32_t sw = SWZ((uint32_t)((nb * 16 + lrow) * 128) + koff);
                ldsm_x4(bh[nb], kvb + half * 8192 + sw);
                ldsm_x4(bl[nb], kvb + 16384 + half * 8192 + sw);
            }
            #pragma unroll
            for (int ni = 0; ni < 8; ++ni) {
                const int nb = ni >> 1, s = ni & 1;
                mma16816(sf[ni], ah, bh[nb][s], bh[nb][s + 2]);
            }
            #pragma unroll
            for (int ni = 0; ni < 8; ++ni) {
                const int nb = ni >> 1, s = ni & 1;
                mma16816(sf[ni], ah, bl[nb][s], bl[nb][s + 2]);
            }
            #pragma unroll
            for (int ni = 0; ni < 8; ++ni) {
                const int nb = ni >> 1, s = ni & 1;
                mma16816(sf[ni], al, bh[nb][s], bh[nb][s + 2]);
            }
        }

        const int colb = j * 64 + (lane & 3) * 2;
        float rmax0 = -INFINITY, rmax1 = -INFINITY;
        #pragma unroll
        for (int ni = 0; ni < 8; ++ni) {
            int c0 = colb + ni * 8, c1 = c0 + 1;
            sf[ni][0] = (c0 <= row0 && row0 - c0 < WINDOW) ? sf[ni][0] * scale : -INFINITY;
            sf[ni][1] = (c1 <= row0 && row0 - c1 < WINDOW) ? sf[ni][1] * scale : -INFINITY;
            sf[ni][2] = (c0 <= row1 && row1 - c0 < WINDOW) ? sf[ni][2] * scale : -INFINITY;
            sf[ni][3] = (c1 <= row1 && row1 - c1 < WINDOW) ? sf[ni][3] * scale : -INFINITY;
            rmax0 = fmaxf(rmax0, fmaxf(sf[ni][0], sf[ni][1]));
            rmax1 = fmaxf(rmax1, fmaxf(sf[ni][2], sf[ni][3]));
        }
        rmax0 = fmaxf(rmax0, __shfl_xor_sync(0xffffffffu, rmax0, 1));
        rmax0 = fmaxf(rmax0, __shfl_xor_sync(0xffffffffu, rmax0, 2));
        rmax1 = fmaxf(rmax1, __shfl_xor_sync(0xffffffffu, rmax1, 1));
        rmax1 = fmaxf(rmax1, __shfl_xor_sync(0xffffffffu, rmax1, 2));

        float mn0 = fmaxf(mst0, rmax0), mn1 = fmaxf(mst1, rmax1);
        float mc0 = fmaxf(mn0, -1e30f), mc1 = fmaxf(mn1, -1e30f);
        float a0 = __expf(fmaxf(mst0, -1e30f) - mc0);
        float a1 = __expf(fmaxf(mst1, -1e30f) - mc1);
        float sum0 = 0.f, sum1 = 0.f;
        #pragma unroll
        for (int ni = 0; ni < 8; ++ni) {
            sf[ni][0] = __expf(sf[ni][0] - mc0);
            sf[ni][1] = __expf(sf[ni][1] - mc0);
            sf[ni][2] = __expf(sf[ni][2] - mc1);
            sf[ni][3] = __expf(sf[ni][3] - mc1);
            sum0 += sf[ni][0] + sf[ni][1];
            sum1 += sf[ni][2] + sf[ni][3];
        }
        sum0 += __shfl_xor_sync(0xffffffffu, sum0, 1);
        sum0 += __shfl_xor_sync(0xffffffffu, sum0, 2);
        sum1 += __shfl_xor_sync(0xffffffffu, sum1, 1);
        sum1 += __shfl_xor_sync(0xffffffffu, sum1, 2);
        mst0 = mn0; mst1 = mn1;
        lst0 = lst0 * a0 + sum0;
        lst1 = lst1 * a1 + sum1;
        #pragma unroll
        for (int nf = 0; nf < 16; ++nf) {
            o[nf][0] *= a0; o[nf][1] *= a0;
            o[nf][2] *= a1; o[nf][3] *= a1;
        }

        #pragma unroll
        for (int ks = 0; ks < 4; ++ks) {
            uint32_t ah[4], al[4];
            packsplit(sf[2 * ks][0],     sf[2 * ks][1],     ah[0], al[0]);
            packsplit(sf[2 * ks][2],     sf[2 * ks][3],     ah[1], al[1]);
            packsplit(sf[2 * ks + 1][0], sf[2 * ks + 1][1], ah[2], al[2]);
            packsplit(sf[2 * ks + 1][2], sf[2 * ks + 1][3], ah[3], al[3]);
            #pragma unroll
            for (int g = 0; g < 8; ++g) {
                const int half = g >> 2;
                uint32_t off = SWZ((uint32_t)((ks * 16 + lrow) * 128 + (g & 3) * 32) + lhi);
                uint32_t vh[4], vl[4];
                ldsm_x4_t(vh, kvb + 32768 + half * 8192 + off);
                ldsm_x4_t(vl, kvb + 49152 + half * 8192 + off);
                mma16816(o[2 * g],     ah, vh[0], vh[1]);
                mma16816(o[2 * g + 1], ah, vh[2], vh[3]);
                mma16816(o[2 * g],     ah, vl[0], vl[1]);
                mma16816(o[2 * g + 1], ah, vl[2], vl[3]);
                mma16816(o[2 * g],     al, vh[0], vh[1]);
                mma16816(o[2 * g + 1], al, vh[2], vh[3]);
            }
        }
        __syncthreads();
    }

    const float inv0 = 1.f / lst0;
    const float inv1 = 1.f / lst1;
    #pragma unroll
    for (int nf = 0; nf < 16; ++nf) {
        int d = h * HDIM + nf * 8 + (lane & 3) * 2;
        *(float2*)&O_g[(size_t)row0 * HID + d] = make_float2(o[nf][0] * inv0, o[nf][1] * inv0);
        *(float2*)&O_g[(size_t)row1 * HID + d] = make_float2(o[nf][2] * inv1, o[nf][3] * inv1);
    }
}

// ---------------------------------------------------------------------------
extern "C" void kernel_launch(void* const* d_in, const int* in_sizes, int n_in,
                              void* d_out, int out_size)
{
    const float* hs  = (const float*)d_in[0];
    const int*   pos = (const int*)d_in[2];
    const float* Wq  = (const float*)d_in[3];
    const float* Wk  = (const float*)d_in[4];
    const float* Wv  = (const float*)d_in[5];
    const float* Wo  = (const float*)d_in[6];
    float* out = (float*)d_out;

    __nv_bfloat16 *qhh, *qll, *khh, *kll, *vhh, *vll;
    float* attf;
    cudaGetSymbolAddress((void**)&qhh, g_Qh);  cudaGetSymbolAddress((void**)&qll, g_Ql);
    cudaGetSymbolAddress((void**)&khh, g_Kh);  cudaGetSymbolAddress((void**)&kll, g_Kl);
    cudaGetSymbolAddress((void**)&vhh, g_Vh);  cudaGetSymbolAddress((void**)&vll, g_Vl);
    cudaGetSymbolAddress((void**)&attf, g_att);

    cudaFuncSetAttribute(gemm_qkv_i8, cudaFuncAttributeMaxDynamicSharedMemorySize, GEMM_SMEM);
    cudaFuncSetAttribute(gemm_wo_i8, cudaFuncAttributeMaxDynamicSharedMemorySize, GEMM_SMEM);
    cudaFuncSetAttribute(attn_mma, cudaFuncAttributeMaxDynamicSharedMemorySize, ATT_SMEM);

    // quantize hs + all weights (warp per row)
    quant_all<<<(NROWS_ALL * 32 + 255) / 256, 256>>>(hs, Wq, Wk, Wv, Wo);

    // fused QKV projection (int8) + RoPE + bf16 split
    gemm_qkv_i8<<<dim3(48, 16), NTHR, GEMM_SMEM>>>(pos);

    // attention (bf16x3 tensor cores) -> fp32 att
    attn_mma<<<dim3(S_LEN / 128, NH), 256, ATT_SMEM>>>(qhh, qll, khh, kll, vhh, vll, attf);

    // quantize attention output
    quant_att_k<<<(S_LEN * 32 + 255) / 256, 256>>>();

    // output projection (int8)
    gemm_wo_i8<<<dim3(HID / 128, S_LEN / 128), NTHR, GEMM_SMEM>>>(out);
}